// round 2
// baseline (speedup 1.0000x reference)
#include <cuda_runtime.h>
#include <cstdint>
#include <cstdio>

#define S_LEN 1024
#define B_SZ  128
#define D_IN  256
#define H_SZ  512
#define C_OUT 128

// ---------------- device scratch (no runtime allocation allowed) ----------------
__device__ float g_T[(size_t)S_LEN * B_SZ * H_SZ];   // x@W_tau_x + b_tau_lin + b_tau   [t][b][h]
__device__ float g_G[(size_t)S_LEN * B_SZ * H_SZ];   // x@W_in + b_in                   [t][b][h]
__device__ float g_mem[B_SZ * H_SZ];                 // final membrane
__device__ int   g_cnt;                              // total spike count

__global__ void init_kernel() { g_cnt = 0; }

// ---------------- Phase 1: fused precompute GEMM ----------------
// C[m, n] = sum_k x_row(m)[k] * Bc[k][n],  m = t*128 + b,  n in [0,1024)
// n <  512 -> G (weights W_in,  bias b_in)
// n >= 512 -> T (weights W_tau[0:256], bias b_tau_lin + b_tau)
__global__ __launch_bounds__(256, 2) void phase1_kernel(
    const float* __restrict__ x, const float* __restrict__ Win,
    const float* __restrict__ bin, const float* __restrict__ Wtau,
    const float* __restrict__ btl, const float* __restrict__ bt)
{
    __shared__ float As[2][16][128];   // transposed: As[k][m]
    __shared__ float Bs[2][16][128];   // Bs[k][n]

    const int tid = threadIdx.x;
    const int m0 = blockIdx.y * 128;
    const int n0 = blockIdx.x * 128;
    const bool isG = (n0 < 512);
    const float* __restrict__ Bp = isG ? (Win + n0) : (Wtau + (n0 - 512));

    // A loads: 2 float4 per thread
    const int q0 = tid, q1 = tid + 256;
    const int ar0 = q0 >> 2, ak0 = (q0 & 3) * 4;
    const int ar1 = q1 >> 2, ak1 = (q1 & 3) * 4;
    const int m_0 = m0 + ar0, m_1 = m0 + ar1;
    const float* ap0 = x + ((size_t)(m_0 & 127) * 1024 + (m_0 >> 7)) * 256 + ak0;
    const float* ap1 = x + ((size_t)(m_1 & 127) * 1024 + (m_1 >> 7)) * 256 + ak1;
    // B loads: 2 float4 per thread
    const int bk0 = q0 >> 5, bn0 = (q0 & 31) * 4;
    const int bk1 = q1 >> 5, bn1 = (q1 & 31) * 4;

    const int tx = tid & 15, ty = tid >> 4;
    const int c0 = tx * 4, c1 = tx * 4 + 64;
    const int r0 = ty * 4, r1 = ty * 4 + 64;

    float acc[8][8];
#pragma unroll
    for (int i = 0; i < 8; i++)
#pragma unroll
        for (int j = 0; j < 8; j++) acc[i][j] = 0.f;

    float4 pa0 = *(const float4*)(ap0);
    float4 pa1 = *(const float4*)(ap1);
    float4 pb0 = *(const float4*)(Bp + (size_t)bk0 * 512 + bn0);
    float4 pb1 = *(const float4*)(Bp + (size_t)bk1 * 512 + bn1);

    As[0][ak0 + 0][ar0] = pa0.x; As[0][ak0 + 1][ar0] = pa0.y;
    As[0][ak0 + 2][ar0] = pa0.z; As[0][ak0 + 3][ar0] = pa0.w;
    As[0][ak1 + 0][ar1] = pa1.x; As[0][ak1 + 1][ar1] = pa1.y;
    As[0][ak1 + 2][ar1] = pa1.z; As[0][ak1 + 3][ar1] = pa1.w;
    *(float4*)&Bs[0][bk0][bn0] = pb0;
    *(float4*)&Bs[0][bk1][bn1] = pb1;
    __syncthreads();

    int p = 0;
    for (int kt = 0; kt < 16; kt++) {
        if (kt < 15) {
            const int kc = (kt + 1) * 16;
            pa0 = *(const float4*)(ap0 + kc);
            pa1 = *(const float4*)(ap1 + kc);
            pb0 = *(const float4*)(Bp + (size_t)(kc + bk0) * 512 + bn0);
            pb1 = *(const float4*)(Bp + (size_t)(kc + bk1) * 512 + bn1);
        }
#pragma unroll
        for (int k = 0; k < 16; k++) {
            float4 a0 = *(const float4*)&As[p][k][r0];
            float4 a1 = *(const float4*)&As[p][k][r1];
            float4 b0 = *(const float4*)&Bs[p][k][c0];
            float4 b1 = *(const float4*)&Bs[p][k][c1];
            float av[8] = {a0.x, a0.y, a0.z, a0.w, a1.x, a1.y, a1.z, a1.w};
            float bv[8] = {b0.x, b0.y, b0.z, b0.w, b1.x, b1.y, b1.z, b1.w};
#pragma unroll
            for (int i = 0; i < 8; i++)
#pragma unroll
                for (int j = 0; j < 8; j++)
                    acc[i][j] = fmaf(av[i], bv[j], acc[i][j]);
        }
        if (kt < 15) {
            const int np = p ^ 1;
            As[np][ak0 + 0][ar0] = pa0.x; As[np][ak0 + 1][ar0] = pa0.y;
            As[np][ak0 + 2][ar0] = pa0.z; As[np][ak0 + 3][ar0] = pa0.w;
            As[np][ak1 + 0][ar1] = pa1.x; As[np][ak1 + 1][ar1] = pa1.y;
            As[np][ak1 + 2][ar1] = pa1.z; As[np][ak1 + 3][ar1] = pa1.w;
            *(float4*)&Bs[np][bk0][bn0] = pb0;
            *(float4*)&Bs[np][bk1][bn1] = pb1;
        }
        __syncthreads();
        p ^= 1;
    }

    float* dst = isG ? g_G : g_T;
    const int coloff = isG ? n0 : (n0 - 512);
    float bias[8];
#pragma unroll
    for (int j = 0; j < 8; j++) {
        const int ncol = (j < 4) ? (c0 + j) : (c1 + j - 4);
        const int gb = coloff + ncol;
        bias[j] = isG ? bin[gb] : (btl[gb] + bt[gb]);
    }
#pragma unroll
    for (int i = 0; i < 8; i++) {
        const int mrow = m0 + ((i < 4) ? (r0 + i) : (r1 + i - 4));
        float4 o0 = make_float4(acc[i][0] + bias[0], acc[i][1] + bias[1],
                                acc[i][2] + bias[2], acc[i][3] + bias[3]);
        float4 o1 = make_float4(acc[i][4] + bias[4], acc[i][5] + bias[5],
                                acc[i][6] + bias[6], acc[i][7] + bias[7]);
        *(float4*)(dst + (size_t)mrow * 512 + coloff + c0) = o0;
        *(float4*)(dst + (size_t)mrow * 512 + coloff + c1) = o1;
    }
}

// ---------------- Phase 2: persistent recurrent kernel (clusters of 8) ----------------
__device__ __forceinline__ unsigned smem_u32_addr(const void* p) {
    unsigned a;
    asm("{ .reg .u64 t; cvta.to.shared.u64 t, %1; cvt.u32.u64 %0, t; }"
        : "=r"(a) : "l"(p));
    return a;
}

#define CLUSTER_BARRIER() \
    asm volatile("barrier.cluster.arrive.aligned;\n\tbarrier.cluster.wait.aligned;" ::: "memory")

__global__ void __cluster_dims__(8, 1, 1) __launch_bounds__(256, 1)
recurrent_kernel(const float* __restrict__ Wtau)
{
    extern __shared__ float sm[];
    float* Wm   = sm;                     // [512][64]   128 KB
    float* memb = sm + 512 * 64;          // [2][8][512]  32 KB
    float* part = memb + 2 * 8 * 512;     // [8][512]     16 KB

    const int tid  = threadIdx.x;
    const int lane = tid & 31;
    const int w    = tid >> 5;
    const int r    = blockIdx.x & 7;          // rank in cluster -> column slice
    const int b0   = (blockIdx.x >> 3) * 8;   // cluster -> 8 batch rows

    // Load this CTA's W_tau_m slice: rows 256..767, cols r*64..r*64+63
    for (int idx = tid; idx < 512 * 64; idx += 256) {
        const int k = idx >> 6, c = idx & 63;
        Wm[idx] = Wtau[(size_t)(256 + k) * 512 + r * 64 + c];
    }
    // Zero both mem buffers
    for (int idx = tid; idx < 2 * 8 * 512; idx += 256) memb[idx] = 0.f;

    const unsigned memb_base = smem_u32_addr(memb);
    CLUSTER_BARRIER();

    const int be  = tid >> 5;            // elementwise batch row 0..7
    const int ce0 = lane, ce1 = lane + 32;
    const int gc0 = r * 64 + ce0, gc1 = r * 64 + ce1;
    const int k0  = w * 64;              // warp K-split

    float cnt = 0.f;

    for (int t = 0; t < S_LEN; t++) {
        const int p = t & 1;
        // Prefetch T/G for elementwise phase (hidden behind the GEMM)
        const size_t row = ((size_t)t * B_SZ + b0 + be) * H_SZ;
        const float Tv0 = g_T[row + gc0], Tv1 = g_T[row + gc1];
        const float Gv0 = g_G[row + gc0], Gv1 = g_G[row + gc1];

        const float* mrow = memb + p * (8 * 512);
        float acc0[8], acc1[8];
#pragma unroll
        for (int b = 0; b < 8; b++) { acc0[b] = 0.f; acc1[b] = 0.f; }

#pragma unroll 4
        for (int kk = 0; kk < 64; kk += 4) {
            const int k = k0 + kk;
            float rm[8][4];
#pragma unroll
            for (int b = 0; b < 8; b++) {
                float4 v = *(const float4*)(mrow + b * 512 + k);
                rm[b][0] = v.x; rm[b][1] = v.y; rm[b][2] = v.z; rm[b][3] = v.w;
            }
#pragma unroll
            for (int j = 0; j < 4; j++) {
                const float w0 = Wm[(k + j) * 64 + lane];
                const float w1 = Wm[(k + j) * 64 + lane + 32];
#pragma unroll
                for (int b = 0; b < 8; b++) {
                    acc0[b] = fmaf(rm[b][j], w0, acc0[b]);
                    acc1[b] = fmaf(rm[b][j], w1, acc1[b]);
                }
            }
        }
#pragma unroll
        for (int b = 0; b < 8; b++) {
            part[w * 512 + b * 64 + lane]      = acc0[b];
            part[w * 512 + b * 64 + lane + 32] = acc1[b];
        }
        __syncthreads();

        // reduce 8 warp-partials + elementwise update for (be, gc0) and (be, gc1)
        float s0 = 0.f, s1 = 0.f;
#pragma unroll
        for (int ww = 0; ww < 8; ww++) {
            s0 += part[ww * 512 + be * 64 + ce0];
            s1 += part[ww * 512 + be * 64 + ce1];
        }
        const float l0 = Tv0 + s0, l1 = Tv1 + s1;
        float beta0 = 1.f / (1.f + expf(-l0));
        float beta1 = 1.f / (1.f + expf(-l1));
        beta0 = fminf(fmaxf(beta0, 0.01f), 0.99f);
        beta1 = fminf(fmaxf(beta1, 0.01f), 0.99f);
        const float mo0 = mrow[be * 512 + gc0];
        const float mo1 = mrow[be * 512 + gc1];
        float mn0 = fmaf(beta0, mo0, Gv0);
        float mn1 = fmaf(beta1, mo1, Gv1);
        const float sp0 = ((mn0 - 1.0f) > 0.0f) ? 1.f : 0.f;
        const float sp1 = ((mn1 - 1.0f) > 0.0f) ? 1.f : 0.f;
        mn0 -= sp0; mn1 -= sp1;
        cnt += sp0 + sp1;

        // broadcast updated slice into every cluster CTA's buffer p^1 (incl. self)
        const unsigned dstb = memb_base + (unsigned)((p ^ 1) * (8 * 512)) * 4u;
        const unsigned a0 = dstb + (unsigned)(be * 512 + gc0) * 4u;
        const unsigned a1 = dstb + (unsigned)(be * 512 + gc1) * 4u;
#pragma unroll
        for (int pr = 0; pr < 8; pr++) {
            unsigned ra0, ra1;
            asm("mapa.shared::cluster.u32 %0, %1, %2;" : "=r"(ra0) : "r"(a0), "r"(pr));
            asm("mapa.shared::cluster.u32 %0, %1, %2;" : "=r"(ra1) : "r"(a1), "r"(pr));
            asm volatile("st.shared::cluster.f32 [%0], %1;" :: "r"(ra0), "f"(mn0));
            asm volatile("st.shared::cluster.f32 [%0], %1;" :: "r"(ra1), "f"(mn1));
        }
        CLUSTER_BARRIER();   // release my writes / acquire peers' writes
    }

    // final mem is in buffer 0 (step 1023 wrote p^1 = 0)
    if (r == 0) {
        for (int idx = tid; idx < 8 * 512; idx += 256)
            g_mem[(size_t)b0 * 512 + idx] = memb[idx];
    }

    // spike-count reduction (exact: all values are small integers)
    __syncthreads();
    part[tid] = cnt;
    __syncthreads();
    if (tid < 128) part[tid] += part[tid + 128];
    __syncthreads();
    if (tid < 64) part[tid] += part[tid + 64];
    __syncthreads();
    if (tid < 32) {
        float v = part[tid] + part[tid + 32];
#pragma unroll
        for (int o = 16; o > 0; o >>= 1) v += __shfl_down_sync(0xffffffffu, v, o);
        if (tid == 0) atomicAdd(&g_cnt, (int)(v + 0.5f));
    }
}

// ---------------- Phase 3: readout GEMM + sparsity ----------------
__global__ void readout_kernel(const float* __restrict__ Wro, const float* __restrict__ bro,
                               float* __restrict__ out, int out_size)
{
    __shared__ float mrow[512];
    const int row = blockIdx.x;
    const int tid = threadIdx.x;   // 128
    for (int i = tid; i < 512; i += 128) mrow[i] = g_mem[(size_t)row * 512 + i];
    __syncthreads();
    float acc = bro[tid];
#pragma unroll 8
    for (int k = 0; k < 512; k++)
        acc = fmaf(mrow[k], Wro[(size_t)k * 128 + tid], acc);
    out[(size_t)row * 128 + tid] = acc;
    if (row == 0 && tid == 0 && out_size > B_SZ * C_OUT) {
        out[B_SZ * C_OUT] = 1.0f - (float)g_cnt / (float)((size_t)S_LEN * B_SZ * H_SZ);
    }
}

// ---------------- launch ----------------
extern "C" void kernel_launch(void* const* d_in, const int* in_sizes, int n_in,
                              void* d_out, int out_size)
{
    const float* x    = (const float*)d_in[0];
    const float* Win  = (const float*)d_in[1];
    const float* bin  = (const float*)d_in[2];
    const float* Wtau = (const float*)d_in[3];
    const float* btl  = (const float*)d_in[4];
    const float* bt   = (const float*)d_in[5];
    const float* Wro  = (const float*)d_in[6];
    const float* bro  = (const float*)d_in[7];

    init_kernel<<<1, 1>>>();

    dim3 g1(8, 1024);   // n-tiles x m-tiles
    phase1_kernel<<<g1, 256>>>(x, Win, bin, Wtau, btl, bt);

    const int rec_smem = (512 * 64 + 2 * 8 * 512 + 8 * 512) * (int)sizeof(float); // 180224 B
    cudaFuncSetAttribute(recurrent_kernel, cudaFuncAttributeMaxDynamicSharedMemorySize, rec_smem);
    recurrent_kernel<<<128, 256, rec_smem>>>(Wtau);

    readout_kernel<<<B_SZ, C_OUT>>>(Wro, bro, (float*)d_out, out_size);
}